// round 1
// baseline (speedup 1.0000x reference)
#include <cuda_runtime.h>
#include <cuda_bf16.h>
#include <math.h>

// Problem constants (fixed by the reference: B=8, D=64, T=512, O=256)
#define PB 8
#define PD 64
#define PT 512
#define PO 256

__device__ __forceinline__ float ex2_approx(float x) {
    float y;
    asm("ex2.approx.ftz.f32 %0, %1;" : "=f"(y) : "f"(x));
    return y;
}

__device__ __forceinline__ float lg2_approx(float x) {
    float y;
    asm("lg2.approx.ftz.f32 %0, %1;" : "=f"(y) : "f"(x));
    return y;
}

__global__ __launch_bounds__(PO, 4)
void interp_kernel(const float* __restrict__ x,
                   const float* __restrict__ grid,
                   const float* __restrict__ kern,
                   float* __restrict__ out) {
    // One block per (b, d) pair. 256 threads, one output column o each.
    const int bd = blockIdx.x;          // 0..511
    const int b  = bd >> 6;
    const int d  = bd & (PD - 1);
    const int o  = threadIdx.x;         // 0..255

    __shared__ __align__(16) float sv[PT];   // vals
    __shared__ __align__(16) float sl[PT];   // log2(max(mask,1e-30))
    __shared__ __align__(16) float st[PT];   // times

    const float* vp = x + (size_t)(b * 3 * PD + d) * PT;
    const float* mp = x + (size_t)(b * 3 * PD + PD + d) * PT;
    const float* tp = x + (size_t)(b * 3 * PD + 2 * PD + d) * PT;

    for (int t = threadIdx.x; t < PT; t += blockDim.x) {
        sv[t] = vp[t];
        sl[t] = lg2_approx(fmaxf(mp[t], 1e-30f));
        st[t] = tp[t];
    }
    __syncthreads();

    // alpha = softplus(kernel[d]); accurate path, negligible cost (once/thread)
    const float k = kern[d];
    const float alpha = (k > 20.0f) ? k : log1pf(expf(k));
    const float c1 = -alpha * 1.4426950408889634f;   // -alpha * log2(e)

    const float g = grid[b * PO + o];

    float aw1 = 0.f, ay1 = 0.f, aw2 = 0.f, ay2 = 0.f;

#pragma unroll 8
    for (int t = 0; t < PT; t++) {
        float dd = st[t] - g;
        float u  = (c1 * dd) * dd;        // c1 * (tv-g)^2   (in log2 domain)
        float l  = sl[t];
        float e1 = ex2_approx(u + l);                   // mm * exp(-a*norm)
        float e2 = ex2_approx(__fmaf_rn(u, 10.f, l));   // mm * exp(-10a*norm)
        float v  = sv[t];
        aw1 += e1;
        ay1 = __fmaf_rn(e1, v, ay1);
        aw2 += e2;
        ay2 = __fmaf_rn(e2, v, ay2);
    }

    // w = ln(sum exp(s)) = log2(aw1) * ln(2)
    const float w = lg2_approx(aw1) * 0.6931471805599453f;

    float* ob = out + (size_t)(b * 3 * PD) * PO + o;
    ob[(size_t)(d) * PO]            = ay1 / aw1;   // y
    ob[(size_t)(PD + d) * PO]       = w;           // w
    ob[(size_t)(2 * PD + d) * PO]   = ay2 / aw2;   // y_trans
}

extern "C" void kernel_launch(void* const* d_in, const int* in_sizes, int n_in,
                              void* d_out, int out_size) {
    const float* x    = (const float*)d_in[0];   // (8, 192, 512)
    const float* grid = (const float*)d_in[1];   // (8, 256)
    const float* kern = (const float*)d_in[2];   // (64,)
    float* out = (float*)d_out;                  // (8, 192, 256)

    interp_kernel<<<PB * PD, PO>>>(x, grid, kern, out);
}